// round 10
// baseline (speedup 1.0000x reference)
#include <cuda_runtime.h>
#include <cuda_fp16.h>
#include <cstdint>
#include <math.h>

// Problem constants
constexpr int B  = 4;
constexpr int N  = 2048;
constexpr int D  = 1024;
constexpr int H  = 16;
constexpr int DK = 64;
constexpr int HD = H * DK;   // 1024

// ---------------------------------------------------------------------------
// Scratch (device globals — no allocation allowed). fp16 hi/lo splits (22 bit).
// ---------------------------------------------------------------------------
__device__ __half g_Qhi[(size_t)B * H * N * DK];  // [bh][n][dk], pre-scaled 0.125
__device__ __half g_Qlo[(size_t)B * H * N * DK];
__device__ __half g_Khi[(size_t)B * H * N * DK];
__device__ __half g_Klo[(size_t)B * H * N * DK];
__device__ __half g_Vhi[(size_t)B * H * N * DK];
__device__ __half g_Vlo[(size_t)B * H * N * DK];
__device__ __half g_Xhi[(size_t)B * N * D];       // X split, [m][k]
__device__ __half g_Xlo[(size_t)B * N * D];
__device__ __half g_WThi[4][(size_t)D * HD];      // W^T split, [n][k] (0=q,1=k,2=v,3=o)
__device__ __half g_WTlo[4][(size_t)D * HD];
__device__ __half g_AThi[(size_t)B * N * HD];     // attention out split, [m][k]
__device__ __half g_ATlo[(size_t)B * N * HD];

// ---------------------------------------------------------------------------
// PTX helpers (generic sm_80+ path — harness PTX targets compute_103, which
// rejects tcgen05/'a'-suffix features; legacy HMMA/ldmatrix/cp.async only)
// ---------------------------------------------------------------------------
__device__ __forceinline__ uint32_t smem_u32(const void* p) {
    uint32_t a;
    asm("{ .reg .u64 t; cvta.to.shared.u64 t, %1; cvt.u32.u64 %0, t; }" : "=r"(a) : "l"(p));
    return a;
}
__device__ __forceinline__ void cp16(uint32_t dst, const void* src) {
    asm volatile("cp.async.cg.shared.global [%0], [%1], 16;" :: "r"(dst), "l"(src));
}
#define CP_COMMIT() asm volatile("cp.async.commit_group;" ::: "memory")
#define CP_WAIT(n)  asm volatile("cp.async.wait_group %0;" :: "n"(n) : "memory")

__device__ __forceinline__ void ldsm4(uint32_t& r0, uint32_t& r1, uint32_t& r2, uint32_t& r3,
                                      uint32_t addr) {
    asm volatile("ldmatrix.sync.aligned.m8n8.x4.shared.b16 {%0,%1,%2,%3}, [%4];"
                 : "=r"(r0), "=r"(r1), "=r"(r2), "=r"(r3) : "r"(addr));
}
__device__ __forceinline__ void ldsm4t(uint32_t& r0, uint32_t& r1, uint32_t& r2, uint32_t& r3,
                                       uint32_t addr) {
    asm volatile("ldmatrix.sync.aligned.m8n8.x4.trans.shared.b16 {%0,%1,%2,%3}, [%4];"
                 : "=r"(r0), "=r"(r1), "=r"(r2), "=r"(r3) : "r"(addr));
}
// fp16 inputs, fp32 accumulate (full accuracy hi*hi product)
__device__ __forceinline__ void mma16816(float* c,
                                         uint32_t a0, uint32_t a1, uint32_t a2, uint32_t a3,
                                         uint32_t b0, uint32_t b1) {
    asm volatile("mma.sync.aligned.m16n8k16.row.col.f32.f16.f16.f32 "
                 "{%0,%1,%2,%3}, {%4,%5,%6,%7}, {%8,%9}, {%0,%1,%2,%3};"
                 : "+f"(c[0]), "+f"(c[1]), "+f"(c[2]), "+f"(c[3])
                 : "r"(a0), "r"(a1), "r"(a2), "r"(a3), "r"(b0), "r"(b1));
}
// fp16 inputs, fp16 accumulate (2x rate; used for the ~2^-11 cross products)
__device__ __forceinline__ void mma16816h(uint32_t* c,
                                          uint32_t a0, uint32_t a1, uint32_t a2, uint32_t a3,
                                          uint32_t b0, uint32_t b1) {
    asm volatile("mma.sync.aligned.m16n8k16.row.col.f16.f16.f16.f16 "
                 "{%0,%1}, {%2,%3,%4,%5}, {%6,%7}, {%0,%1};"
                 : "+r"(c[0]), "+r"(c[1])
                 : "r"(a0), "r"(a1), "r"(a2), "r"(a3), "r"(b0), "r"(b1));
}
// split v0,v1 into packed fp16 hi pair (return) and lo pair (out param)
__device__ __forceinline__ uint32_t packsplit(float v0, float v1, uint32_t& lo) {
    const __half h0 = __float2half_rn(v0);
    const __half h1 = __float2half_rn(v1);
    __half2 hp; hp.x = h0; hp.y = h1;
    __half2 lp;
    lp.x = __float2half_rn(v0 - __half2float(h0));
    lp.y = __float2half_rn(v1 - __half2float(h1));
    lo = *reinterpret_cast<uint32_t*>(&lp);
    return *reinterpret_cast<uint32_t*>(&hp);
}
__device__ __forceinline__ float2 h2f2(uint32_t u) {
    return __half22float2(*reinterpret_cast<__half2*>(&u));
}

// ---------------------------------------------------------------------------
// fp16-split HMMA GEMM body: C[128,128] = A[128,1024]@B, B given as B^T [n][k].
// C = Ah*Bh (f32 acc) + [Ah*Bl + Al*Bh] (f16 acc, merged at epilogue).
// 4-stage cp.async ring, single __syncthreads per K-chunk.
// ---------------------------------------------------------------------------
constexpr int APITCH_B = 80;
constexpr int ARR_B    = 128 * APITCH_B;
constexpr int STAGE_B  = 4 * ARR_B;          // 40960
constexpr int GSTAGES  = 4;
constexpr int GSMEM    = GSTAGES * STAGE_B;  // 163840

__device__ __forceinline__ void gemm_mma_body(
    const __half* __restrict__ Ahi, const __half* __restrict__ Alo,
    const __half* __restrict__ Bhi, const __half* __restrict__ Blo,
    int rowBase, int colBase, char* sm, float acc[4][4][4], uint32_t accL[4][4][2])
{
    const int tid  = threadIdx.x;
    const int lane = tid & 31;
    const int w    = tid >> 5;
    const int wm   = (w >> 2) * 64;
    const int wn   = (w & 3) * 32;
    const uint32_t sb = smem_u32(sm);

    auto load_stage = [&](int s, int k0) {
        const uint32_t base = sb + s * STAGE_B;
        #pragma unroll
        for (int a = 0; a < 4; ++a) {
            const __half* src = (a == 0) ? Ahi : (a == 1) ? Alo : (a == 2) ? Bhi : Blo;
            const int rb = (a < 2) ? rowBase : colBase;
            #pragma unroll
            for (int t = 0; t < 2; ++t) {
                const int idx = tid * 2 + t;
                const int r = idx >> 2, ch = idx & 3;
                cp16(base + a * ARR_B + r * APITCH_B + ch * 16,
                     src + (size_t)(rb + r) * D + k0 + ch * 8);
            }
        }
    };

    auto comp = [&](int s) {
        const uint32_t base = sb + s * STAGE_B;
        #pragma unroll
        for (int k16 = 0; k16 < 2; ++k16) {
            uint32_t Ah[4][4], Al[4][4], Bh[2][4], Bl[2][4];
            #pragma unroll
            for (int mi = 0; mi < 4; ++mi) {
                const uint32_t addr = base + (wm + mi * 16 + (lane & 15)) * APITCH_B
                                      + k16 * 32 + (lane >> 4) * 16;
                ldsm4(Ah[mi][0], Ah[mi][1], Ah[mi][2], Ah[mi][3], addr);
                ldsm4(Al[mi][0], Al[mi][1], Al[mi][2], Al[mi][3], addr + ARR_B);
            }
            #pragma unroll
            for (int np = 0; np < 2; ++np) {
                const int nrow = wn + np * 16 + (lane & 7) + ((lane >> 4) << 3);
                const uint32_t addr = base + 2 * ARR_B + nrow * APITCH_B
                                      + k16 * 32 + ((lane >> 3) & 1) * 16;
                ldsm4(Bh[np][0], Bh[np][1], Bh[np][2], Bh[np][3], addr);
                ldsm4(Bl[np][0], Bl[np][1], Bl[np][2], Bl[np][3], addr + ARR_B);
            }
            // hi*hi -> fp32 acc
            #pragma unroll
            for (int mi = 0; mi < 4; ++mi)
                #pragma unroll
                for (int nf = 0; nf < 4; ++nf) {
                    const int np = nf >> 1, hh = (nf & 1) * 2;
                    mma16816(acc[mi][nf], Ah[mi][0], Ah[mi][1], Ah[mi][2], Ah[mi][3],
                             Bh[np][hh], Bh[np][hh + 1]);
                }
            // cross terms -> fp16 acc (2x rate)
            #pragma unroll
            for (int mi = 0; mi < 4; ++mi)
                #pragma unroll
                for (int nf = 0; nf < 4; ++nf) {
                    const int np = nf >> 1, hh = (nf & 1) * 2;
                    mma16816h(accL[mi][nf], Ah[mi][0], Ah[mi][1], Ah[mi][2], Ah[mi][3],
                              Bl[np][hh], Bl[np][hh + 1]);
                }
            #pragma unroll
            for (int mi = 0; mi < 4; ++mi)
                #pragma unroll
                for (int nf = 0; nf < 4; ++nf) {
                    const int np = nf >> 1, hh = (nf & 1) * 2;
                    mma16816h(accL[mi][nf], Al[mi][0], Al[mi][1], Al[mi][2], Al[mi][3],
                              Bh[np][hh], Bh[np][hh + 1]);
                }
        }
    };

    constexpr int NC = D / 32;   // 32 chunks
    load_stage(0, 0);            CP_COMMIT();
    load_stage(1, 32);           CP_COMMIT();
    load_stage(2, 64);           CP_COMMIT();
    for (int c = 0; c < NC; ++c) {
        CP_WAIT(2);
        __syncthreads();
        if (c + 3 < NC) load_stage((c + 3) & 3, (c + 3) * 32);
        CP_COMMIT();
        comp(c & 3);
    }
}

// QKV projection: epilogue writes fp16 hi/lo per-head tensors (Q pre-scaled)
__global__ __launch_bounds__(256, 1) void qkv_mma() {
    extern __shared__ char sm[];
    const int z = blockIdx.z;
    const int rowBase = blockIdx.y * 128, colBase = blockIdx.x * 128;
    float acc[4][4][4];
    uint32_t accL[4][4][2];
    #pragma unroll
    for (int i = 0; i < 4; ++i)
        #pragma unroll
        for (int j = 0; j < 4; ++j) {
            #pragma unroll
            for (int k = 0; k < 4; ++k) acc[i][j][k] = 0.f;
            accL[i][j][0] = 0u; accL[i][j][1] = 0u;
        }

    gemm_mma_body(g_Xhi, g_Xlo, g_WThi[z], g_WTlo[z], rowBase, colBase, sm, acc, accL);

    __half* Ohi = (z == 0) ? g_Qhi : (z == 1) ? g_Khi : g_Vhi;
    __half* Olo = (z == 0) ? g_Qlo : (z == 1) ? g_Klo : g_Vlo;
    const float scale = (z == 0) ? 0.125f : 1.0f;

    const int lane = threadIdx.x & 31, w = threadIdx.x >> 5;
    const int wm = (w >> 2) * 64, wn = (w & 3) * 32;
    #pragma unroll
    for (int mi = 0; mi < 4; ++mi)
        #pragma unroll
        for (int nf = 0; nf < 4; ++nf) {
            const int r0 = rowBase + wm + mi * 16 + (lane >> 2);
            const int c0 = colBase + wn + nf * 8 + (lane & 3) * 2;
            const int hh = c0 >> 6, dd = c0 & 63;
            const float2 lo01 = h2f2(accL[mi][nf][0]);
            const float2 lo23 = h2f2(accL[mi][nf][1]);
            const float v0 = acc[mi][nf][0] + lo01.x, v1 = acc[mi][nf][1] + lo01.y;
            const float v2 = acc[mi][nf][2] + lo23.x, v3 = acc[mi][nf][3] + lo23.y;
            #pragma unroll
            for (int rr = 0; rr < 2; ++rr) {
                const int r = r0 + rr * 8;
                const int b = r >> 11, n = r & (N - 1);
                const size_t idx = (((size_t)(b * H + hh)) * N + n) * DK + dd;
                uint32_t lo;
                const uint32_t hi = (rr == 0) ? packsplit(v0 * scale, v1 * scale, lo)
                                              : packsplit(v2 * scale, v3 * scale, lo);
                *reinterpret_cast<uint32_t*>(Ohi + idx) = hi;
                *reinterpret_cast<uint32_t*>(Olo + idx) = lo;
            }
        }
}

// Output projection: attention-out (split) @ Wo -> d_out fp32
__global__ __launch_bounds__(256, 1) void out_mma(float* __restrict__ Cout) {
    extern __shared__ char sm[];
    const int rowBase = blockIdx.y * 128, colBase = blockIdx.x * 128;
    float acc[4][4][4];
    uint32_t accL[4][4][2];
    #pragma unroll
    for (int i = 0; i < 4; ++i)
        #pragma unroll
        for (int j = 0; j < 4; ++j) {
            #pragma unroll
            for (int k = 0; k < 4; ++k) acc[i][j][k] = 0.f;
            accL[i][j][0] = 0u; accL[i][j][1] = 0u;
        }

    gemm_mma_body(g_AThi, g_ATlo, g_WThi[3], g_WTlo[3], rowBase, colBase, sm, acc, accL);

    const int lane = threadIdx.x & 31, w = threadIdx.x >> 5;
    const int wm = (w >> 2) * 64, wn = (w & 3) * 32;
    #pragma unroll
    for (int mi = 0; mi < 4; ++mi)
        #pragma unroll
        for (int nf = 0; nf < 4; ++nf) {
            const int r0 = rowBase + wm + mi * 16 + (lane >> 2);
            const int c0 = colBase + wn + nf * 8 + (lane & 3) * 2;
            const float2 lo01 = h2f2(accL[mi][nf][0]);
            const float2 lo23 = h2f2(accL[mi][nf][1]);
            Cout[(size_t)r0 * HD + c0]           = acc[mi][nf][0] + lo01.x;
            Cout[(size_t)r0 * HD + c0 + 1]       = acc[mi][nf][1] + lo01.y;
            Cout[(size_t)(r0 + 8) * HD + c0]     = acc[mi][nf][2] + lo23.x;
            Cout[(size_t)(r0 + 8) * HD + c0 + 1] = acc[mi][nf][3] + lo23.y;
        }
}

// ---------------------------------------------------------------------------
// Precision-split conversion passes
// ---------------------------------------------------------------------------
__global__ void convX(const float* __restrict__ X) {
    const size_t i = ((size_t)blockIdx.x * 256 + threadIdx.x) * 2;
    const float2 v = *(const float2*)(X + i);
    uint32_t lo;
    const uint32_t hi = packsplit(v.x, v.y, lo);
    *reinterpret_cast<uint32_t*>(g_Xhi + i) = hi;
    *reinterpret_cast<uint32_t*>(g_Xlo + i) = lo;
}

__global__ void convW(const float* __restrict__ Wq, const float* __restrict__ Wk,
                      const float* __restrict__ Wv, const float* __restrict__ Wo) {
    const int z = blockIdx.z;
    const float* W = (z == 0) ? Wq : (z == 1) ? Wk : (z == 2) ? Wv : Wo;
    __half* Th = g_WThi[z];
    __half* Tl = g_WTlo[z];
    __shared__ float t[32][33];
    const int k0 = blockIdx.x * 32, n0 = blockIdx.y * 32;
    #pragma unroll
    for (int j = 0; j < 32; j += 8)
        t[threadIdx.y + j][threadIdx.x] = W[(size_t)(k0 + threadIdx.y + j) * HD + n0 + threadIdx.x];
    __syncthreads();
    #pragma unroll
    for (int j = 0; j < 32; j += 8) {
        const int n = n0 + threadIdx.y + j, k = k0 + threadIdx.x;
        const float v = t[threadIdx.x][threadIdx.y + j];
        const __half h = __float2half_rn(v);
        Th[(size_t)n * D + k] = h;
        Tl[(size_t)n * D + k] = __float2half_rn(v - __half2float(h));
    }
}

// ---------------------------------------------------------------------------
// Tensor-core flash attention (causal). 128 q-rows per CTA, 8 warps.
// S: Qh*Kh (f32) + [Qh*Kl + Ql*Kh] (f16 acc).  O: same structure with P,V.
// 3-stage KV ring, single __syncthreads per tile.
// ---------------------------------------------------------------------------
constexpr int FP     = 144;            // smem pitch (128B data + 16B pad)
constexpr int KVARR  = 64 * FP;        // 9216
constexpr int KVSTG  = 4 * KVARR;      // Kh|Kl|Vh|Vl: 36864
constexpr int QARR   = 128 * FP;       // 18432
constexpr int FSTAGES = 3;
constexpr int FSMEM  = 2 * QARR + FSTAGES * KVSTG;   // 147456

__global__ __launch_bounds__(256, 1)
void flash_mma() {
    extern __shared__ char sm[];
    const uint32_t sb = smem_u32(sm);
    const int tid = threadIdx.x, lane = tid & 31, w = tid >> 5;
    const int bh = blockIdx.y;
    const int qt = gridDim.x - 1 - blockIdx.x;        // long blocks first
    const int q0 = qt * 128;
    const int b = bh >> 4, h = bh & (H - 1);
    const int wm = w * 16;

    const __half* Qh = g_Qhi + (size_t)bh * N * DK;
    const __half* Ql = g_Qlo + (size_t)bh * N * DK;
    const __half* Kh = g_Khi + (size_t)bh * N * DK;
    const __half* Kl = g_Klo + (size_t)bh * N * DK;
    const __half* Vh = g_Vhi + (size_t)bh * N * DK;
    const __half* Vl = g_Vlo + (size_t)bh * N * DK;

    const uint32_t qhiS = sb, qloS = sb + QARR, stS = sb + 2 * QARR;

    auto load_kv = [&](int s, int j0) {
        const uint32_t base = stS + s * KVSTG;
        #pragma unroll
        for (int t = 0; t < 2; ++t) {
            const int i = tid + t * 256;
            const int r = i >> 3, ch = i & 7;
            const uint32_t off = r * FP + ch * 16;
            const size_t gi = (size_t)(j0 + r) * DK + ch * 8;
            cp16(base + off,             Kh + gi);
            cp16(base + KVARR + off,     Kl + gi);
            cp16(base + 2 * KVARR + off, Vh + gi);
            cp16(base + 3 * KVARR + off, Vl + gi);
        }
    };

    const int jmax = 2 * qt + 1;

    for (int i = tid; i < 1024; i += 256) {
        const int r = i >> 3, ch = i & 7;
        const size_t gi = (size_t)(q0 + r) * DK + ch * 8;
        cp16(qhiS + r * FP + ch * 16, Qh + gi);
        cp16(qloS + r * FP + ch * 16, Ql + gi);
    }
    load_kv(0, 0);
    CP_COMMIT();
    load_kv(1, 64);
    CP_COMMIT();

    float m0 = -1e30f, m1 = -1e30f, l0 = 0.f, l1 = 0.f;
    float oAcc[8][4];
    #pragma unroll
    for (int i = 0; i < 8; ++i)
        #pragma unroll
        for (int e = 0; e < 4; ++e) oAcc[i][e] = 0.f;

    uint32_t qah[4][4], qal[4][4];
    bool qloaded = false;
    int kvbuf = 0;

    for (int jt = 0; jt <= jmax; ++jt) {
        const int j0 = jt * 64;
        CP_WAIT(1);
        __syncthreads();
        if (jt + 2 <= jmax) {
            int nb = kvbuf + 2; if (nb >= 3) nb -= 3;
            load_kv(nb, (jt + 2) * 64);
        }
        CP_COMMIT();

        if (!qloaded) {
            #pragma unroll
            for (int kf = 0; kf < 4; ++kf) {
                const uint32_t addr = qhiS + (wm + (lane & 15)) * FP + kf * 32 + (lane >> 4) * 16;
                ldsm4(qah[kf][0], qah[kf][1], qah[kf][2], qah[kf][3], addr);
                ldsm4(qal[kf][0], qal[kf][1], qal[kf][2], qal[kf][3], addr + QARR);
            }
            qloaded = true;
        }

        const uint32_t khS = stS + kvbuf * KVSTG;
        const uint32_t vhS = khS + 2 * KVARR;
        if (++kvbuf == 3) kvbuf = 0;

        // ---- S = Q @ K^T : hi*hi f32; cross f16 acc ----
        float s[8][4];
        uint32_t sL[8][2];
        #pragma unroll
        for (int i = 0; i < 8; ++i) {
            #pragma unroll
            for (int e = 0; e < 4; ++e) s[i][e] = 0.f;
            sL[i][0] = 0u; sL[i][1] = 0u;
        }

        #pragma unroll
        for (int kf = 0; kf < 4; ++kf) {
            uint32_t kb[4][4], klb[4][4];
            #pragma unroll
            for (int ng = 0; ng < 4; ++ng) {
                const uint32_t addr = khS + (ng * 16 + (lane & 7) + ((lane >> 4) << 3)) * FP
                                      + kf * 32 + ((lane >> 3) & 1) * 16;
                ldsm4(kb[ng][0], kb[ng][1], kb[ng][2], kb[ng][3], addr);
                ldsm4(klb[ng][0], klb[ng][1], klb[ng][2], klb[ng][3], addr + KVARR);
            }
            #pragma unroll
            for (int ng = 0; ng < 4; ++ng)
                #pragma unroll
                for (int nf = 0; nf < 2; ++nf)
                    mma16816(s[ng * 2 + nf], qah[kf][0], qah[kf][1], qah[kf][2], qah[kf][3],
                             kb[ng][nf * 2], kb[ng][nf * 2 + 1]);
            #pragma unroll
            for (int ng = 0; ng < 4; ++ng)
                #pragma unroll
                for (int nf = 0; nf < 2; ++nf)
                    mma16816h(sL[ng * 2 + nf], qah[kf][0], qah[kf][1], qah[kf][2], qah[kf][3],
                              klb[ng][nf * 2], klb[ng][nf * 2 + 1]);
            #pragma unroll
            for (int ng = 0; ng < 4; ++ng)
                #pragma unroll
                for (int nf = 0; nf < 2; ++nf)
                    mma16816h(sL[ng * 2 + nf], qal[kf][0], qal[kf][1], qal[kf][2], qal[kf][3],
                              kb[ng][nf * 2], kb[ng][nf * 2 + 1]);
        }
        // merge f16 cross-acc into f32 S
        #pragma unroll
        for (int ni = 0; ni < 8; ++ni) {
            const float2 c01 = h2f2(sL[ni][0]);
            const float2 c23 = h2f2(sL[ni][1]);
            s[ni][0] += c01.x; s[ni][1] += c01.y;
            s[ni][2] += c23.x; s[ni][3] += c23.y;
        }

        // ---- causal mask ----
        const int gr0 = q0 + wm + (lane >> 2);
        if (j0 + 64 > q0 + wm) {
            #pragma unroll
            for (int ni = 0; ni < 8; ++ni)
                #pragma unroll
                for (int e = 0; e < 4; ++e) {
                    const int col = j0 + ni * 8 + (lane & 3) * 2 + (e & 1);
                    const int row = gr0 + (e >> 1) * 8;
                    if (col > row) s[ni][e] = -1e30f;
                }
        }

        // ---- online softmax ----
        float rm0 = -1e30f, rm1 = -1e30f;
        #pragma unroll
        for (int ni = 0; ni < 8; ++ni) {
            rm0 = fmaxf(rm0, fmaxf(s[ni][0], s[ni][1]));
            rm1 = fmaxf(rm1, fmaxf(s[ni][2], s[ni][3]));
        }
        rm0 = fmaxf(rm0, __shfl_xor_sync(0xffffffffu, rm0, 1));
        rm0 = fmaxf(rm0, __shfl_xor_sync(0xffffffffu, rm0, 2));
        rm1 = fmaxf(rm1, __shfl_xor_sync(0xffffffffu, rm1, 1));
        rm1 = fmaxf(rm1, __shfl_xor_sync(0xffffffffu, rm1, 2));

        const float mn0 = fmaxf(m0, rm0), mn1 = fmaxf(m1, rm1);
        const float a0 = __expf(m0 - mn0), a1 = __expf(m1 - mn1);
        m0 = mn0; m1 = mn1;

        float rs0 = 0.f, rs1 = 0.f;
        #pragma unroll
        for (int ni = 0; ni < 8; ++ni) {
            s[ni][0] = __expf(s[ni][0] - mn0); rs0 += s[ni][0];
            s[ni][1] = __expf(s[ni][1] - mn0); rs0 += s[ni][1];
            s[ni][2] = __expf(s[ni][2] - mn1); rs1 += s[ni][2];
            s[ni][3] = __expf(s[ni][3] - mn1); rs1 += s[ni][3];
        }
        rs0 += __shfl_xor_sync(0xffffffffu, rs0, 1);
        rs0 += __shfl_xor_sync(0xffffffffu, rs0, 2);
        rs1 += __shfl_xor_sync(0xffffffffu, rs1, 1);
        rs1 += __shfl_xor_sync(0xffffffffu, rs1, 2);
        l0 = l0 * a0 + rs0;
        l1 = l1 * a1 + rs1;

        #pragma unroll
        for (int ni = 0; ni < 8; ++ni) {
            oAcc[ni][0] *= a0; oAcc[ni][1] *= a0;
            oAcc[ni][2] *= a1; oAcc[ni][3] *= a1;
        }

        // ---- P -> fp16 hi/lo A-fragments (register-only) ----
        uint32_t pah[4][4], pal[4][4];
        #pragma unroll
        for (int kf = 0; kf < 4; ++kf) {
            pah[kf][0] = packsplit(s[2 * kf][0],     s[2 * kf][1],     pal[kf][0]);
            pah[kf][1] = packsplit(s[2 * kf][2],     s[2 * kf][3],     pal[kf][1]);
            pah[kf][2] = packsplit(s[2 * kf + 1][0], s[2 * kf + 1][1], pal[kf][2]);
            pah[kf][3] = packsplit(s[2 * kf + 1][2], s[2 * kf + 1][3], pal[kf][3]);
        }

        // ---- O += P @ V : hi*hi f32; cross f16 acc (per-tile, merged below) ----
        uint32_t oL[8][2];
        #pragma unroll
        for (int ni = 0; ni < 8; ++ni) { oL[ni][0] = 0u; oL[ni][1] = 0u; }

        #pragma unroll
        for (int kf = 0; kf < 4; ++kf) {
            uint32_t vb[4][4], vlb[4][4];
            #pragma unroll
            for (int ng = 0; ng < 4; ++ng) {
                const uint32_t addr = vhS + (kf * 16 + (lane & 15)) * FP
                                      + ng * 32 + (lane >> 4) * 16;
                ldsm4t(vb[ng][0], vb[ng][1], vb[ng][2], vb[ng][3], addr);
                ldsm4t(vlb[ng][0], vlb[ng][1], vlb[ng][2], vlb[ng][3], addr + KVARR);
            }
            #pragma unroll
            for (int ng = 0; ng < 4; ++ng)
                #pragma unroll
                for (int nf = 0; nf < 2; ++nf)
                    mma16816(oAcc[ng * 2 + nf], pah[kf][0], pah[kf][1], pah[kf][2], pah[kf][3],
                             vb[ng][nf * 2], vb[ng][nf * 2 + 1]);
            #pragma unroll
            for (int ng = 0; ng < 4; ++ng)
                #pragma unroll
                for (int nf = 0; nf < 2; ++nf)
                    mma16816h(oL[ng * 2 + nf], pah[kf][0], pah[kf][1], pah[kf][2], pah[kf][3],
                              vlb[ng][nf * 2], vlb[ng][nf * 2 + 1]);
            #pragma unroll
            for (int ng = 0; ng < 4; ++ng)
                #pragma unroll
                for (int nf = 0; nf < 2; ++nf)
                    mma16816h(oL[ng * 2 + nf], pal[kf][0], pal[kf][1], pal[kf][2], pal[kf][3],
                              vb[ng][nf * 2], vb[ng][nf * 2 + 1]);
        }
        // merge per-tile f16 cross-acc into fp32 O (before next tile's rescale)
        #pragma unroll
        for (int ni = 0; ni < 8; ++ni) {
            const float2 c01 = h2f2(oL[ni][0]);
            const float2 c23 = h2f2(oL[ni][1]);
            oAcc[ni][0] += c01.x; oAcc[ni][1] += c01.y;
            oAcc[ni][2] += c23.x; oAcc[ni][3] += c23.y;
        }
        // no trailing sync: 3-stage ring + top-of-loop barrier covers reuse
    }

    // ---- epilogue: normalize, split to fp16 hi/lo for output projection ----
    const float inv0 = 1.0f / l0, inv1 = 1.0f / l1;
    const int r0 = q0 + wm + (lane >> 2);
    #pragma unroll
    for (int ni = 0; ni < 8; ++ni) {
        const int col = h * DK + ni * 8 + (lane & 3) * 2;
        uint32_t lo;
        uint32_t hi = packsplit(oAcc[ni][0] * inv0, oAcc[ni][1] * inv0, lo);
        size_t idx = ((size_t)b * N + r0) * HD + col;
        *reinterpret_cast<uint32_t*>(g_AThi + idx) = hi;
        *reinterpret_cast<uint32_t*>(g_ATlo + idx) = lo;
        hi = packsplit(oAcc[ni][2] * inv1, oAcc[ni][3] * inv1, lo);
        idx = ((size_t)b * N + r0 + 8) * HD + col;
        *reinterpret_cast<uint32_t*>(g_AThi + idx) = hi;
        *reinterpret_cast<uint32_t*>(g_ATlo + idx) = lo;
    }
}

// ---------------------------------------------------------------------------
extern "C" void kernel_launch(void* const* d_in, const int* in_sizes, int n_in,
                              void* d_out, int out_size) {
    const float* X  = (const float*)d_in[0];
    // d_in[1] = mask (pure causal -> applied analytically)
    const float* Wq = (const float*)d_in[2];
    const float* Wk = (const float*)d_in[3];
    const float* Wv = (const float*)d_in[4];
    const float* Wo = (const float*)d_in[5];
    float* out = (float*)d_out;

    cudaFuncSetAttribute(qkv_mma,   cudaFuncAttributeMaxDynamicSharedMemorySize, GSMEM);
    cudaFuncSetAttribute(out_mma,   cudaFuncAttributeMaxDynamicSharedMemorySize, GSMEM);
    cudaFuncSetAttribute(flash_mma, cudaFuncAttributeMaxDynamicSharedMemorySize, FSMEM);

    // 0) precision-split conversions
    convX<<<(B * N * D / 2) / 256, 256>>>(X);
    convW<<<dim3(D / 32, HD / 32, 4), dim3(32, 8)>>>(Wq, Wk, Wv, Wo);

    // 1) QKV projections (HMMA), epilogue emits fp16 hi/lo Q/K/V
    qkv_mma<<<dim3(HD / 128, (B * N) / 128, 3), 256, GSMEM>>>();   // (8, 64, 3)

    // 2) causal flash attention on tensor cores
    flash_mma<<<dim3(N / 128, B * H), 256, FSMEM>>>();             // (16, 64)

    // 3) output projection (HMMA)
    out_mma<<<dim3(HD / 128, (B * N) / 128), 256, GSMEM>>>(out);   // (8, 64)
}

// round 11
// speedup vs baseline: 1.3157x; 1.3157x over previous
#include <cuda_runtime.h>
#include <cuda_fp16.h>
#include <cstdint>
#include <math.h>

// Problem constants
constexpr int B  = 4;
constexpr int N  = 2048;
constexpr int D  = 1024;
constexpr int H  = 16;
constexpr int DK = 64;
constexpr int HD = H * DK;   // 1024

// ---------------------------------------------------------------------------
// Scratch (device globals — no allocation allowed). fp16 hi/lo splits.
// K/V need no lo arrays: their quantization is accepted (2-product flash).
// ---------------------------------------------------------------------------
__device__ __half g_Qhi[(size_t)B * H * N * DK];  // [bh][n][dk], pre-scaled 0.125
__device__ __half g_Qlo[(size_t)B * H * N * DK];
__device__ __half g_Khi[(size_t)B * H * N * DK];
__device__ __half g_Vhi[(size_t)B * H * N * DK];
__device__ __half g_Xhi[(size_t)B * N * D];       // X split, [m][k]
__device__ __half g_Xlo[(size_t)B * N * D];
__device__ __half g_WThi[4][(size_t)D * HD];      // W^T split, [n][k] (0=q,1=k,2=v,3=o)
__device__ __half g_WTlo[4][(size_t)D * HD];      // lo used only by out_mma (z=3)
__device__ __half g_AThi[(size_t)B * N * HD];     // attention out split, [m][k]
__device__ __half g_ATlo[(size_t)B * N * HD];

// ---------------------------------------------------------------------------
// PTX helpers (generic sm_80+ path — harness PTX targets compute_103, which
// rejects tcgen05/'a'-suffix features; legacy HMMA/ldmatrix/cp.async only)
// ---------------------------------------------------------------------------
__device__ __forceinline__ uint32_t smem_u32(const void* p) {
    uint32_t a;
    asm("{ .reg .u64 t; cvta.to.shared.u64 t, %1; cvt.u32.u64 %0, t; }" : "=r"(a) : "l"(p));
    return a;
}
__device__ __forceinline__ void cp16(uint32_t dst, const void* src) {
    asm volatile("cp.async.cg.shared.global [%0], [%1], 16;" :: "r"(dst), "l"(src));
}
#define CP_COMMIT() asm volatile("cp.async.commit_group;" ::: "memory")
#define CP_WAIT(n)  asm volatile("cp.async.wait_group %0;" :: "n"(n) : "memory")

__device__ __forceinline__ void ldsm4(uint32_t& r0, uint32_t& r1, uint32_t& r2, uint32_t& r3,
                                      uint32_t addr) {
    asm volatile("ldmatrix.sync.aligned.m8n8.x4.shared.b16 {%0,%1,%2,%3}, [%4];"
                 : "=r"(r0), "=r"(r1), "=r"(r2), "=r"(r3) : "r"(addr));
}
__device__ __forceinline__ void ldsm4t(uint32_t& r0, uint32_t& r1, uint32_t& r2, uint32_t& r3,
                                       uint32_t addr) {
    asm volatile("ldmatrix.sync.aligned.m8n8.x4.trans.shared.b16 {%0,%1,%2,%3}, [%4];"
                 : "=r"(r0), "=r"(r1), "=r"(r2), "=r"(r3) : "r"(addr));
}
// fp16 inputs, fp32 accumulate
__device__ __forceinline__ void mma16816(float* c,
                                         uint32_t a0, uint32_t a1, uint32_t a2, uint32_t a3,
                                         uint32_t b0, uint32_t b1) {
    asm volatile("mma.sync.aligned.m16n8k16.row.col.f32.f16.f16.f32 "
                 "{%0,%1,%2,%3}, {%4,%5,%6,%7}, {%8,%9}, {%0,%1,%2,%3};"
                 : "+f"(c[0]), "+f"(c[1]), "+f"(c[2]), "+f"(c[3])
                 : "r"(a0), "r"(a1), "r"(a2), "r"(a3), "r"(b0), "r"(b1));
}
// split v0,v1 into packed fp16 hi pair (return) and lo pair (out param)
__device__ __forceinline__ uint32_t packsplit(float v0, float v1, uint32_t& lo) {
    const __half h0 = __float2half_rn(v0);
    const __half h1 = __float2half_rn(v1);
    __half2 hp; hp.x = h0; hp.y = h1;
    __half2 lp;
    lp.x = __float2half_rn(v0 - __half2float(h0));
    lp.y = __float2half_rn(v1 - __half2float(h1));
    lo = *reinterpret_cast<uint32_t*>(&lp);
    return *reinterpret_cast<uint32_t*>(&hp);
}
__device__ __forceinline__ uint32_t packh2(float v0, float v1) {
    __half2 hp; hp.x = __float2half_rn(v0); hp.y = __float2half_rn(v1);
    return *reinterpret_cast<uint32_t*>(&hp);
}

// ---------------------------------------------------------------------------
// fp16-split HMMA GEMM body: C[128,128] = A[128,1024]@B, B given as B^T [n][k].
// NARR=3 (2-product): C = Ah*Bh + Al*Bh (B quantization accepted, ~2e-4)
// NARR=4 (3-product): C = Ah*Bh + Ah*Bl + Al*Bh (full correction)
// 4-stage cp.async ring, single __syncthreads per K-chunk. f32 accumulate.
// ---------------------------------------------------------------------------
constexpr int APITCH_B = 80;
constexpr int ARR_B    = 128 * APITCH_B;     // 10240

template <int NARR>
__device__ __forceinline__ void gemm_mma_body(
    const __half* __restrict__ Ahi, const __half* __restrict__ Alo,
    const __half* __restrict__ Bhi, const __half* __restrict__ Blo,
    int rowBase, int colBase, char* sm, float acc[4][4][4])
{
    constexpr int STG = NARR * ARR_B;
    const int tid  = threadIdx.x;
    const int lane = tid & 31;
    const int w    = tid >> 5;
    const int wm   = (w >> 2) * 64;
    const int wn   = (w & 3) * 32;
    const uint32_t sb = smem_u32(sm);

    auto load_stage = [&](int s, int k0) {
        const uint32_t base = sb + s * STG;
        #pragma unroll
        for (int a = 0; a < NARR; ++a) {
            const __half* src = (a == 0) ? Ahi : (a == 1) ? Alo : (a == 2) ? Bhi : Blo;
            const int rb = (a < 2) ? rowBase : colBase;
            #pragma unroll
            for (int t = 0; t < 2; ++t) {
                const int idx = tid * 2 + t;
                const int r = idx >> 2, ch = idx & 3;
                cp16(base + a * ARR_B + r * APITCH_B + ch * 16,
                     src + (size_t)(rb + r) * D + k0 + ch * 8);
            }
        }
    };

    auto comp = [&](int s) {
        const uint32_t base = sb + s * STG;
        #pragma unroll
        for (int k16 = 0; k16 < 2; ++k16) {
            uint32_t Ah[4][4], Al[4][4], Bh[2][4], Bl[2][4];
            #pragma unroll
            for (int mi = 0; mi < 4; ++mi) {
                const uint32_t addr = base + (wm + mi * 16 + (lane & 15)) * APITCH_B
                                      + k16 * 32 + (lane >> 4) * 16;
                ldsm4(Ah[mi][0], Ah[mi][1], Ah[mi][2], Ah[mi][3], addr);
                ldsm4(Al[mi][0], Al[mi][1], Al[mi][2], Al[mi][3], addr + ARR_B);
            }
            #pragma unroll
            for (int np = 0; np < 2; ++np) {
                const int nrow = wn + np * 16 + (lane & 7) + ((lane >> 4) << 3);
                const uint32_t addr = base + 2 * ARR_B + nrow * APITCH_B
                                      + k16 * 32 + ((lane >> 3) & 1) * 16;
                ldsm4(Bh[np][0], Bh[np][1], Bh[np][2], Bh[np][3], addr);
                if (NARR == 4)
                    ldsm4(Bl[np][0], Bl[np][1], Bl[np][2], Bl[np][3], addr + ARR_B);
            }
            // Ah*Bh (16 independent accs)
            #pragma unroll
            for (int mi = 0; mi < 4; ++mi)
                #pragma unroll
                for (int nf = 0; nf < 4; ++nf) {
                    const int np = nf >> 1, hh = (nf & 1) * 2;
                    mma16816(acc[mi][nf], Ah[mi][0], Ah[mi][1], Ah[mi][2], Ah[mi][3],
                             Bh[np][hh], Bh[np][hh + 1]);
                }
            // Al*Bh
            #pragma unroll
            for (int mi = 0; mi < 4; ++mi)
                #pragma unroll
                for (int nf = 0; nf < 4; ++nf) {
                    const int np = nf >> 1, hh = (nf & 1) * 2;
                    mma16816(acc[mi][nf], Al[mi][0], Al[mi][1], Al[mi][2], Al[mi][3],
                             Bh[np][hh], Bh[np][hh + 1]);
                }
            // Ah*Bl (3-product only)
            if (NARR == 4) {
                #pragma unroll
                for (int mi = 0; mi < 4; ++mi)
                    #pragma unroll
                    for (int nf = 0; nf < 4; ++nf) {
                        const int np = nf >> 1, hh = (nf & 1) * 2;
                        mma16816(acc[mi][nf], Ah[mi][0], Ah[mi][1], Ah[mi][2], Ah[mi][3],
                                 Bl[np][hh], Bl[np][hh + 1]);
                    }
            }
        }
    };

    constexpr int NC = D / 32;   // 32 chunks
    load_stage(0, 0);            CP_COMMIT();
    load_stage(1, 32);           CP_COMMIT();
    load_stage(2, 64);           CP_COMMIT();
    for (int c = 0; c < NC; ++c) {
        CP_WAIT(2);
        __syncthreads();
        if (c + 3 < NC) load_stage((c + 3) & 3, (c + 3) * 32);
        CP_COMMIT();
        comp(c & 3);
    }
}

constexpr int GSMEM_QKV = 4 * 3 * ARR_B;   // 122880
constexpr int GSMEM_OUT = 4 * 4 * ARR_B;   // 163840

// QKV projection (2-product). Epilogue: Q gets hi+lo (pre-scaled); K,V hi only.
__global__ __launch_bounds__(256, 1) void qkv_mma() {
    extern __shared__ char sm[];
    const int z = blockIdx.z;
    const int rowBase = blockIdx.y * 128, colBase = blockIdx.x * 128;
    float acc[4][4][4];
    #pragma unroll
    for (int i = 0; i < 4; ++i)
        #pragma unroll
        for (int j = 0; j < 4; ++j)
            #pragma unroll
            for (int k = 0; k < 4; ++k) acc[i][j][k] = 0.f;

    gemm_mma_body<3>(g_Xhi, g_Xlo, g_WThi[z], nullptr, rowBase, colBase, sm, acc);

    const int lane = threadIdx.x & 31, w = threadIdx.x >> 5;
    const int wm = (w >> 2) * 64, wn = (w & 3) * 32;
    #pragma unroll
    for (int mi = 0; mi < 4; ++mi)
        #pragma unroll
        for (int nf = 0; nf < 4; ++nf) {
            const int r0 = rowBase + wm + mi * 16 + (lane >> 2);
            const int c0 = colBase + wn + nf * 8 + (lane & 3) * 2;
            const int hh = c0 >> 6, dd = c0 & 63;
            #pragma unroll
            for (int rr = 0; rr < 2; ++rr) {
                const int r = r0 + rr * 8;
                const int b = r >> 11, n = r & (N - 1);
                const size_t idx = (((size_t)(b * H + hh)) * N + n) * DK + dd;
                const float v0 = acc[mi][nf][rr * 2], v1 = acc[mi][nf][rr * 2 + 1];
                if (z == 0) {
                    uint32_t lo;
                    const uint32_t hi = packsplit(v0 * 0.125f, v1 * 0.125f, lo);
                    *reinterpret_cast<uint32_t*>(g_Qhi + idx) = hi;
                    *reinterpret_cast<uint32_t*>(g_Qlo + idx) = lo;
                } else {
                    __half* Ohi = (z == 1) ? g_Khi : g_Vhi;
                    *reinterpret_cast<uint32_t*>(Ohi + idx) = packh2(v0, v1);
                }
            }
        }
}

// Output projection (3-product, fully corrected): AT @ Wo -> d_out fp32
__global__ __launch_bounds__(256, 1) void out_mma(float* __restrict__ Cout) {
    extern __shared__ char sm[];
    const int rowBase = blockIdx.y * 128, colBase = blockIdx.x * 128;
    float acc[4][4][4];
    #pragma unroll
    for (int i = 0; i < 4; ++i)
        #pragma unroll
        for (int j = 0; j < 4; ++j)
            #pragma unroll
            for (int k = 0; k < 4; ++k) acc[i][j][k] = 0.f;

    gemm_mma_body<4>(g_AThi, g_ATlo, g_WThi[3], g_WTlo[3], rowBase, colBase, sm, acc);

    const int lane = threadIdx.x & 31, w = threadIdx.x >> 5;
    const int wm = (w >> 2) * 64, wn = (w & 3) * 32;
    #pragma unroll
    for (int mi = 0; mi < 4; ++mi)
        #pragma unroll
        for (int nf = 0; nf < 4; ++nf) {
            const int r0 = rowBase + wm + mi * 16 + (lane >> 2);
            const int c0 = colBase + wn + nf * 8 + (lane & 3) * 2;
            #pragma unroll
            for (int e = 0; e < 4; ++e)
                Cout[(size_t)(r0 + (e >> 1) * 8) * HD + c0 + (e & 1)] = acc[mi][nf][e];
        }
}

// ---------------------------------------------------------------------------
// Precision-split conversion passes
// ---------------------------------------------------------------------------
__global__ void convX(const float* __restrict__ X) {
    const size_t i = ((size_t)blockIdx.x * 256 + threadIdx.x) * 2;
    const float2 v = *(const float2*)(X + i);
    uint32_t lo;
    const uint32_t hi = packsplit(v.x, v.y, lo);
    *reinterpret_cast<uint32_t*>(g_Xhi + i) = hi;
    *reinterpret_cast<uint32_t*>(g_Xlo + i) = lo;
}

__global__ void convW(const float* __restrict__ Wq, const float* __restrict__ Wk,
                      const float* __restrict__ Wv, const float* __restrict__ Wo) {
    const int z = blockIdx.z;
    const float* W = (z == 0) ? Wq : (z == 1) ? Wk : (z == 2) ? Wv : Wo;
    __half* Th = g_WThi[z];
    __half* Tl = g_WTlo[z];
    __shared__ float t[32][33];
    const int k0 = blockIdx.x * 32, n0 = blockIdx.y * 32;
    #pragma unroll
    for (int j = 0; j < 32; j += 8)
        t[threadIdx.y + j][threadIdx.x] = W[(size_t)(k0 + threadIdx.y + j) * HD + n0 + threadIdx.x];
    __syncthreads();
    #pragma unroll
    for (int j = 0; j < 32; j += 8) {
        const int n = n0 + threadIdx.y + j, k = k0 + threadIdx.x;
        const float v = t[threadIdx.x][threadIdx.y + j];
        const __half h = __float2half_rn(v);
        Th[(size_t)n * D + k] = h;
        Tl[(size_t)n * D + k] = __float2half_rn(v - __half2float(h));
    }
}

// ---------------------------------------------------------------------------
// Tensor-core flash attention (causal), 2-product numerics:
// S = Qh*Kh + Ql*Kh (K quantization accepted).
// O = Ph*Vh + Pl*Vh (V quantization accepted).
// 128 q-rows per CTA, 8 warps. 3-stage KV ring (Kh|Vh only), f32 acc.
// ---------------------------------------------------------------------------
constexpr int FP     = 144;            // smem pitch (128B data + 16B pad)
constexpr int KVARR  = 64 * FP;        // 9216
constexpr int KVSTG  = 2 * KVARR;      // Kh|Vh: 18432
constexpr int QARR   = 128 * FP;       // 18432
constexpr int FSTAGES = 3;
constexpr int FSMEM  = 2 * QARR + FSTAGES * KVSTG;   // 92160

__global__ __launch_bounds__(256, 1)
void flash_mma() {
    extern __shared__ char sm[];
    const uint32_t sb = smem_u32(sm);
    const int tid = threadIdx.x, lane = tid & 31, w = tid >> 5;
    const int bh = blockIdx.y;
    const int qt = gridDim.x - 1 - blockIdx.x;        // long blocks first
    const int q0 = qt * 128;
    const int b = bh >> 4, h = bh & (H - 1);
    const int wm = w * 16;

    const __half* Qh = g_Qhi + (size_t)bh * N * DK;
    const __half* Ql = g_Qlo + (size_t)bh * N * DK;
    const __half* Kh = g_Khi + (size_t)bh * N * DK;
    const __half* Vh = g_Vhi + (size_t)bh * N * DK;

    const uint32_t qhiS = sb, qloS = sb + QARR, stS = sb + 2 * QARR;

    auto load_kv = [&](int s, int j0) {
        const uint32_t base = stS + s * KVSTG;
        #pragma unroll
        for (int t = 0; t < 2; ++t) {
            const int i = tid + t * 256;
            const int r = i >> 3, ch = i & 7;
            const uint32_t off = r * FP + ch * 16;
            const size_t gi = (size_t)(j0 + r) * DK + ch * 8;
            cp16(base + off,         Kh + gi);
            cp16(base + KVARR + off, Vh + gi);
        }
    };

    const int jmax = 2 * qt + 1;

    for (int i = tid; i < 1024; i += 256) {
        const int r = i >> 3, ch = i & 7;
        const size_t gi = (size_t)(q0 + r) * DK + ch * 8;
        cp16(qhiS + r * FP + ch * 16, Qh + gi);
        cp16(qloS + r * FP + ch * 16, Ql + gi);
    }
    load_kv(0, 0);
    CP_COMMIT();
    load_kv(1, 64);
    CP_COMMIT();

    float m0 = -1e30f, m1 = -1e30f, l0 = 0.f, l1 = 0.f;
    float oAcc[8][4];
    #pragma unroll
    for (int i = 0; i < 8; ++i)
        #pragma unroll
        for (int e = 0; e < 4; ++e) oAcc[i][e] = 0.f;

    uint32_t qah[4][4], qal[4][4];
    bool qloaded = false;
    int kvbuf = 0;

    for (int jt = 0; jt <= jmax; ++jt) {
        const int j0 = jt * 64;
        CP_WAIT(1);
        __syncthreads();
        if (jt + 2 <= jmax) {
            int nb = kvbuf + 2; if (nb >= 3) nb -= 3;
            load_kv(nb, (jt + 2) * 64);
        }
        CP_COMMIT();

        if (!qloaded) {
            #pragma unroll
            for (int kf = 0; kf < 4; ++kf) {
                const uint32_t addr = qhiS + (wm + (lane & 15)) * FP + kf * 32 + (lane >> 4) * 16;
                ldsm4(qah[kf][0], qah[kf][1], qah[kf][2], qah[kf][3], addr);
                ldsm4(qal[kf][0], qal[kf][1], qal[kf][2], qal[kf][3], addr + QARR);
            }
            qloaded = true;
        }

        const uint32_t khS = stS + kvbuf * KVSTG;
        const uint32_t vhS = khS + KVARR;
        if (++kvbuf == 3) kvbuf = 0;

        // ---- S = (Qh + Ql) @ Kh^T ----
        float s[8][4];
        #pragma unroll
        for (int i = 0; i < 8; ++i)
            #pragma unroll
            for (int e = 0; e < 4; ++e) s[i][e] = 0.f;

        #pragma unroll
        for (int kf = 0; kf < 4; ++kf) {
            uint32_t kb[4][4];
            #pragma unroll
            for (int ng = 0; ng < 4; ++ng) {
                const uint32_t addr = khS + (ng * 16 + (lane & 7) + ((lane >> 4) << 3)) * FP
                                      + kf * 32 + ((lane >> 3) & 1) * 16;
                ldsm4(kb[ng][0], kb[ng][1], kb[ng][2], kb[ng][3], addr);
            }
            #pragma unroll
            for (int ng = 0; ng < 4; ++ng)
                #pragma unroll
                for (int nf = 0; nf < 2; ++nf)
                    mma16816(s[ng * 2 + nf], qah[kf][0], qah[kf][1], qah[kf][2], qah[kf][3],
                             kb[ng][nf * 2], kb[ng][nf * 2 + 1]);
            #pragma unroll
            for (int ng = 0; ng < 4; ++ng)
                #pragma unroll
                for (int nf = 0; nf < 2; ++nf)
                    mma16816(s[ng * 2 + nf], qal[kf][0], qal[kf][1], qal[kf][2], qal[kf][3],
                             kb[ng][nf * 2], kb[ng][nf * 2 + 1]);
        }

        // ---- causal mask ----
        const int gr0 = q0 + wm + (lane >> 2);
        if (j0 + 64 > q0 + wm) {
            #pragma unroll
            for (int ni = 0; ni < 8; ++ni)
                #pragma unroll
                for (int e = 0; e < 4; ++e) {
                    const int col = j0 + ni * 8 + (lane & 3) * 2 + (e & 1);
                    const int row = gr0 + (e >> 1) * 8;
                    if (col > row) s[ni][e] = -1e30f;
                }
        }

        // ---- online softmax ----
        float rm0 = -1e30f, rm1 = -1e30f;
        #pragma unroll
        for (int ni = 0; ni < 8; ++ni) {
            rm0 = fmaxf(rm0, fmaxf(s[ni][0], s[ni][1]));
            rm1 = fmaxf(rm1, fmaxf(s[ni][2], s[ni][3]));
        }
        rm0 = fmaxf(rm0, __shfl_xor_sync(0xffffffffu, rm0, 1));
        rm0 = fmaxf(rm0, __shfl_xor_sync(0xffffffffu, rm0, 2));
        rm1 = fmaxf(rm1, __shfl_xor_sync(0xffffffffu, rm1, 1));
        rm1 = fmaxf(rm1, __shfl_xor_sync(0xffffffffu, rm1, 2));

        const float mn0 = fmaxf(m0, rm0), mn1 = fmaxf(m1, rm1);
        const float a0 = __expf(m0 - mn0), a1 = __expf(m1 - mn1);
        m0 = mn0; m1 = mn1;

        float rs0 = 0.f, rs1 = 0.f;
        #pragma unroll
        for (int ni = 0; ni < 8; ++ni) {
            s[ni][0] = __expf(s[ni][0] - mn0); rs0 += s[ni][0];
            s[ni][1] = __expf(s[ni][1] - mn0); rs0 += s[ni][1];
            s[ni][2] = __expf(s[ni][2] - mn1); rs1 += s[ni][2];
            s[ni][3] = __expf(s[ni][3] - mn1); rs1 += s[ni][3];
        }
        rs0 += __shfl_xor_sync(0xffffffffu, rs0, 1);
        rs0 += __shfl_xor_sync(0xffffffffu, rs0, 2);
        rs1 += __shfl_xor_sync(0xffffffffu, rs1, 1);
        rs1 += __shfl_xor_sync(0xffffffffu, rs1, 2);
        l0 = l0 * a0 + rs0;
        l1 = l1 * a1 + rs1;

        #pragma unroll
        for (int ni = 0; ni < 8; ++ni) {
            oAcc[ni][0] *= a0; oAcc[ni][1] *= a0;
            oAcc[ni][2] *= a1; oAcc[ni][3] *= a1;
        }

        // ---- P -> fp16 hi/lo A-fragments (register-only) ----
        uint32_t pah[4][4], pal[4][4];
        #pragma unroll
        for (int kf = 0; kf < 4; ++kf) {
            pah[kf][0] = packsplit(s[2 * kf][0],     s[2 * kf][1],     pal[kf][0]);
            pah[kf][1] = packsplit(s[2 * kf][2],     s[2 * kf][3],     pal[kf][1]);
            pah[kf][2] = packsplit(s[2 * kf + 1][0], s[2 * kf + 1][1], pal[kf][2]);
            pah[kf][3] = packsplit(s[2 * kf + 1][2], s[2 * kf + 1][3], pal[kf][3]);
        }

        // ---- O += (Ph + Pl) @ Vh ----
        #pragma unroll
        for (int kf = 0; kf < 4; ++kf) {
            uint32_t vb[4][4];
            #pragma unroll
            for (int ng = 0; ng < 4; ++ng) {
                const uint32_t addr = vhS + (kf * 16 + (lane & 15)) * FP
                                      + ng * 32 + (lane >> 4) * 16;
                ldsm4t(vb[ng][0], vb[ng][1], vb[ng][2], vb[ng][3], addr);
            }
            #pragma unroll
            for (int ng = 0; ng < 4; ++ng)
                #pragma unroll
                for (int nf = 0; nf < 2; ++nf)
                    mma16816(oAcc[ng * 2 + nf], pah[kf][0], pah[kf][1], pah[kf][2], pah[kf][3],
                             vb[ng][nf * 2], vb[ng][nf * 2 + 1]);
            #pragma unroll
            for (int ng = 0; ng < 4; ++ng)
                #pragma unroll
                for (int nf = 0; nf < 2; ++nf)
                    mma16816(oAcc[ng * 2 + nf], pal[kf][0], pal[kf][1], pal[kf][2], pal[kf][3],
                             vb[ng][nf * 2], vb[ng][nf * 2 + 1]);
        }
        // no trailing sync: 3-stage ring + top-of-loop barrier covers reuse
    }

    // ---- epilogue: normalize, split to fp16 hi/lo for output projection ----
    const float inv0 = 1.0f / l0, inv1 = 1.0f / l1;
    const int r0 = q0 + wm + (lane >> 2);
    #pragma unroll
    for (int ni = 0; ni < 8; ++ni) {
        const int col = h * DK + ni * 8 + (lane & 3) * 2;
        uint32_t lo;
        uint32_t hi = packsplit(oAcc[ni][0] * inv0, oAcc[ni][1] * inv0, lo);
        size_t idx = ((size_t)b * N + r0) * HD + col;
        *reinterpret_cast<uint32_t*>(g_AThi + idx) = hi;
        *reinterpret_cast<uint32_t*>(g_ATlo + idx) = lo;
        hi = packsplit(oAcc[ni][2] * inv1, oAcc[ni][3] * inv1, lo);
        idx = ((size_t)b * N + r0 + 8) * HD + col;
        *reinterpret_cast<uint32_t*>(g_AThi + idx) = hi;
        *reinterpret_cast<uint32_t*>(g_ATlo + idx) = lo;
    }
}

// ---------------------------------------------------------------------------
extern "C" void kernel_launch(void* const* d_in, const int* in_sizes, int n_in,
                              void* d_out, int out_size) {
    const float* X  = (const float*)d_in[0];
    // d_in[1] = mask (pure causal -> applied analytically)
    const float* Wq = (const float*)d_in[2];
    const float* Wk = (const float*)d_in[3];
    const float* Wv = (const float*)d_in[4];
    const float* Wo = (const float*)d_in[5];
    float* out = (float*)d_out;

    cudaFuncSetAttribute(qkv_mma,   cudaFuncAttributeMaxDynamicSharedMemorySize, GSMEM_QKV);
    cudaFuncSetAttribute(out_mma,   cudaFuncAttributeMaxDynamicSharedMemorySize, GSMEM_OUT);
    cudaFuncSetAttribute(flash_mma, cudaFuncAttributeMaxDynamicSharedMemorySize, FSMEM);

    // 0) precision-split conversions
    convX<<<(B * N * D / 2) / 256, 256>>>(X);
    convW<<<dim3(D / 32, HD / 32, 4), dim3(32, 8)>>>(Wq, Wk, Wv, Wo);

    // 1) QKV projections (2-product HMMA)
    qkv_mma<<<dim3(HD / 128, (B * N) / 128, 3), 256, GSMEM_QKV>>>();   // (8, 64, 3)

    // 2) causal flash attention (2-product HMMA)
    flash_mma<<<dim3(N / 128, B * H), 256, FSMEM>>>();                 // (16, 64)

    // 3) output projection (3-product HMMA, fully corrected)
    out_mma<<<dim3(HD / 128, (B * N) / 128), 256, GSMEM_OUT>>>(out);   // (8, 64)
}